// round 3
// baseline (speedup 1.0000x reference)
#include <cuda_runtime.h>

#define NPTS   2097152
#define NSTR   500
#define NCELLS 4096          // 16^3 grid over [-1,1]^3
#define TPB    256
#define PPT    4
#define PTS_PER_BLOCK (TPB * PPT)   // 1024

typedef unsigned long long ull;
typedef unsigned int uint;

// ---- scratch (__device__ globals: allowed) ----
__device__ float4 g_tmpPts[NPTS];      // warped coords (w unused)
__device__ int    g_cellOf[NPTS];
__device__ int    g_order[NPTS];       // sorted position -> original index
__device__ uint   g_cursor[NCELLS];    // counts -> offsets -> cursors
__device__ float4 g_s0[NSTR];          // {-cx, -cy, cr, cg}
__device__ float4 g_s1[NSTR];          // {cb, dens, -cz, b=5r+0.5}

// ---- f32x2 packed helpers (sm_103a) ----
__device__ __forceinline__ ull pk2(float lo, float hi) {
    ull r; asm("mov.b64 %0, {%1,%2};" : "=l"(r) : "f"(lo), "f"(hi)); return r;
}
__device__ __forceinline__ void upk2(ull v, float& lo, float& hi) {
    asm("mov.b64 {%0,%1}, %2;" : "=f"(lo), "=f"(hi) : "l"(v));
}
__device__ __forceinline__ ull add2(ull a, ull b) {
    ull r; asm("add.rn.f32x2 %0, %1, %2;" : "=l"(r) : "l"(a), "l"(b)); return r;
}
__device__ __forceinline__ ull mul2(ull a, ull b) {
    ull r; asm("mul.rn.f32x2 %0, %1, %2;" : "=l"(r) : "l"(a), "l"(b)); return r;
}
__device__ __forceinline__ ull fma2_(ull a, ull b, ull c) {
    ull r; asm("fma.rn.f32x2 %0, %1, %2, %3;" : "=l"(r) : "l"(a), "l"(b), "l"(c)); return r;
}
__device__ __forceinline__ float sqap(float x) {
    float y; asm("sqrt.approx.f32 %0, %1;" : "=f"(y) : "f"(x)); return y;
}
// t = saturate(dist * (-5.0) + b)   -- FFMA-imm form, rt=1
__device__ __forceinline__ float fmasat_m5(float dist, float b) {
    float d; asm("fma.rn.sat.f32 %0, %1, 0fC0A00000, %2;" : "=f"(d) : "f"(dist), "f"(b));
    return d;
}

// 4-bit Morton spread: bits to 9,6,3,0
__device__ __forceinline__ uint mort4(uint v) {
    v &= 15u;
    v = (v | (v << 4)) & 0xC3u;
    v = (v | (v << 2)) & 0x249u;
    return v;
}

// ---- Pass A: zero cursors + preprocess strokes ----
__global__ void prep_kernel(const float4* __restrict__ shape,
                            const float*  __restrict__ color,
                            const float*  __restrict__ alpha)
{
    int i = blockIdx.x * blockDim.x + threadIdx.x;   // 0..4095
    if (i < NCELLS) g_cursor[i] = 0u;
    if (i < NSTR) {
        float4 sp = shape[i];
        float cr = color[3 * i + 0];
        float cg = color[3 * i + 1];
        float cb = color[3 * i + 2];
        float dens = fmaxf(alpha[i], 0.0f) * 50.0f;
        g_s0[i] = make_float4(-sp.x, -sp.y, cr, cg);
        g_s1[i] = make_float4(cb, dens, -sp.z, fmaf(sp.w, 5.0f, 0.5f));
    }
}

// ---- Pass B: warp coords, write coords output, bin-count ----
__global__ __launch_bounds__(TPB)
void bin_kernel(const float* __restrict__ coords, float* __restrict__ out)
{
    int i = blockIdx.x * TPB + threadIdx.x;
    float x = coords[3 * i + 0];
    float y = coords[3 * i + 1];
    float z = coords[3 * i + 2];
    float n2 = fmaf(x, x, fmaf(y, y, z * z));
    float n  = sqrtf(n2);
    float scale = 0.5f;
    if (n > 1.0f) scale = (2.0f - 1.0f / n) * (0.5f / n);
    float px = x * scale, py = y * scale, pz = z * scale;

    out[4 * NPTS + 3 * i + 0] = px;
    out[4 * NPTS + 3 * i + 1] = py;
    out[4 * NPTS + 3 * i + 2] = pz;
    g_tmpPts[i] = make_float4(px, py, pz, 0.0f);

    int ix = min(15, max(0, (int)((px + 1.0f) * 8.0f)));
    int iy = min(15, max(0, (int)((py + 1.0f) * 8.0f)));
    int iz = min(15, max(0, (int)((pz + 1.0f) * 8.0f)));
    int cell = (int)(mort4((uint)ix) | (mort4((uint)iy) << 1) | (mort4((uint)iz) << 2));
    g_cellOf[i] = cell;
    atomicAdd(&g_cursor[cell], 1u);
}

// ---- Pass C: single-block exclusive scan of 4096 counts (in place) ----
__global__ __launch_bounds__(1024)
void scan_kernel()
{
    __shared__ uint warpsum[32];
    int t = threadIdx.x;
    int lane = t & 31, wid = t >> 5;

    uint v[4];
    uint base_i = (uint)t * 4u;
#pragma unroll
    for (int j = 0; j < 4; j++) v[j] = g_cursor[base_i + j];
    uint local = v[0] + v[1] + v[2] + v[3];

    uint x = local;
#pragma unroll
    for (int d = 1; d < 32; d <<= 1) {
        uint y = __shfl_up_sync(0xffffffffu, x, d);
        if (lane >= d) x += y;
    }
    if (lane == 31) warpsum[wid] = x;
    __syncthreads();
    if (wid == 0) {
        uint w = warpsum[lane];
#pragma unroll
        for (int d = 1; d < 32; d <<= 1) {
            uint y = __shfl_up_sync(0xffffffffu, w, d);
            if (lane >= d) w += y;
        }
        warpsum[lane] = w;
    }
    __syncthreads();
    uint base = (wid ? warpsum[wid - 1] : 0u) + (x - local);
#pragma unroll
    for (int j = 0; j < 4; j++) {
        g_cursor[base_i + j] = base;
        base += v[j];
    }
}

// ---- Pass D: scatter ORIGINAL INDEX (4B) into sorted order; 4 pts/thread for MLP ----
__global__ __launch_bounds__(TPB)
void scatter_kernel()
{
    int g = blockIdx.x * TPB + threadIdx.x;
    int4 c = ((const int4*)g_cellOf)[g];
    int i0 = g * 4;
    uint p0 = atomicAdd(&g_cursor[c.x], 1u);
    uint p1 = atomicAdd(&g_cursor[c.y], 1u);
    uint p2 = atomicAdd(&g_cursor[c.z], 1u);
    uint p3 = atomicAdd(&g_cursor[c.w], 1u);
    g_order[p0] = i0 + 0;
    g_order[p1] = i0 + 1;
    g_order[p2] = i0 + 2;
    g_order[p3] = i0 + 3;
}

// ---- Pass E: main blend over culled strokes (pair-packed f32x2) ----
__global__ __launch_bounds__(TPB)
void main_kernel(float* __restrict__ out)
{
    __shared__ float4 cs0[NSTR];
    __shared__ float4 cs1[NSTR];
    __shared__ uint  wcnt[8];
    __shared__ float red[8][6];

    const int tid = threadIdx.x;
    const int lane = tid & 31, wid = tid >> 5;
    const int base = blockIdx.x * PTS_PER_BLOCK + tid;

    float px[PPT], py[PPT], pzv[PPT];
    int   orig[PPT];

    float mnx =  1e30f, mny =  1e30f, mnz =  1e30f;
    float mxx = -1e30f, mxy = -1e30f, mxz = -1e30f;

#pragma unroll
    for (int k = 0; k < PPT; k++) {
        int idx = g_order[base + k * TPB];
        orig[k] = idx;
        float4 p = g_tmpPts[idx];
        px[k] = p.x; py[k] = p.y; pzv[k] = p.z;
        mnx = fminf(mnx, p.x); mxx = fmaxf(mxx, p.x);
        mny = fminf(mny, p.y); mxy = fmaxf(mxy, p.y);
        mnz = fminf(mnz, p.z); mxz = fmaxf(mxz, p.z);
    }

    // pack points into pairs: lane-lo = point 2q, lane-hi = point 2q+1
    ull pX[2], pY[2], pZ[2];
    ull hR[2], hG[2], hB[2], hD[2], hW[2];
#pragma unroll
    for (int q = 0; q < 2; q++) {
        pX[q] = pk2(px[2*q], px[2*q+1]);
        pY[q] = pk2(py[2*q], py[2*q+1]);
        pZ[q] = pk2(pzv[2*q], pzv[2*q+1]);
        hR[q] = 0ULL; hG[q] = 0ULL; hB[q] = 0ULL; hD[q] = 0ULL;
        hW[q] = pk2(1.0f, 1.0f);
    }

    // block bbox reduce
#pragma unroll
    for (int d = 16; d; d >>= 1) {
        mnx = fminf(mnx, __shfl_xor_sync(0xffffffffu, mnx, d));
        mny = fminf(mny, __shfl_xor_sync(0xffffffffu, mny, d));
        mnz = fminf(mnz, __shfl_xor_sync(0xffffffffu, mnz, d));
        mxx = fmaxf(mxx, __shfl_xor_sync(0xffffffffu, mxx, d));
        mxy = fmaxf(mxy, __shfl_xor_sync(0xffffffffu, mxy, d));
        mxz = fmaxf(mxz, __shfl_xor_sync(0xffffffffu, mxz, d));
    }
    if (lane == 0) {
        red[wid][0] = mnx; red[wid][1] = mny; red[wid][2] = mnz;
        red[wid][3] = mxx; red[wid][4] = mxy; red[wid][5] = mxz;
    }
    __syncthreads();
#pragma unroll
    for (int ww = 0; ww < 8; ww++) {
        mnx = fminf(mnx, red[ww][0]); mny = fminf(mny, red[ww][1]); mnz = fminf(mnz, red[ww][2]);
        mxx = fmaxf(mxx, red[ww][3]); mxy = fmaxf(mxy, red[ww][4]); mxz = fmaxf(mxz, red[ww][5]);
    }
    __syncthreads();

    // ordered stream compaction of strokes intersecting the bbox
    int nlist = 0;
#pragma unroll 1
    for (int r = 0; r < 2; r++) {
        int s = r * TPB + tid;
        bool keep = false;
        float4 a0, a1;
        if (s < NSTR) {
            a0 = g_s0[s]; a1 = g_s1[s];
            float cx = -a0.x, cy = -a0.y, cz = -a1.z;
            float qx = fminf(fmaxf(cx, mnx), mxx);
            float qy = fminf(fmaxf(cy, mny), mxy);
            float qz = fminf(fmaxf(cz, mnz), mxz);
            float dx = cx - qx, dy = cy - qy, dz = cz - qz;
            float d2 = fmaf(dx, dx, fmaf(dy, dy, dz * dz));
            keep = 25.0f * d2 < a1.w * a1.w;   // dist(bbox, center) < r + 0.1
        }
        uint m = __ballot_sync(0xffffffffu, keep);
        if (lane == 0) wcnt[wid] = (uint)__popc(m);
        __syncthreads();
        int off = nlist, tot = nlist;
#pragma unroll
        for (int ww = 0; ww < 8; ww++) {
            if (ww < wid) off += (int)wcnt[ww];
            tot += (int)wcnt[ww];
        }
        if (keep) {
            int pos = off + __popc(m & ((1u << lane) - 1u));
            cs0[pos] = a0;
            cs1[pos] = a1;
        }
        nlist = tot;
        __syncthreads();
    }

    // sequential blend (order preserved), pair-packed
#pragma unroll 1
    for (int s = 0; s < nlist; s++) {
        float4 s0 = cs0[s];
        float4 s1 = cs1[s];
        ull ncx2 = pk2(s0.x, s0.x);
        ull ncy2 = pk2(s0.y, s0.y);
        ull ncz2 = pk2(s1.z, s1.z);
        ull cR2  = pk2(s0.z, s0.z);
        ull cG2  = pk2(s0.w, s0.w);
        ull cB2  = pk2(s1.x, s1.x);
        ull cD2  = pk2(s1.y, s1.y);
        float bb = s1.w;
#pragma unroll
        for (int q = 0; q < 2; q++) {
            ull dX = add2(pX[q], ncx2);
            ull dY = add2(pY[q], ncy2);
            ull dZ = add2(pZ[q], ncz2);
            ull d2p = fma2_(dZ, dZ, fma2_(dY, dY, mul2(dX, dX)));
            float d2a, d2b; upk2(d2p, d2a, d2b);
            float ta = fmasat_m5(sqap(d2a), bb);
            float tb = fmasat_m5(sqap(d2b), bb);
            ull tp  = pk2(ta, tb);
            ull ntp = tp ^ 0x8000000080000000ULL;   // (-ta, -tb) : alu pipe
            hR[q] = fma2_(tp, cR2, fma2_(ntp, hR[q], hR[q]));
            hG[q] = fma2_(tp, cG2, fma2_(ntp, hG[q], hG[q]));
            hB[q] = fma2_(tp, cB2, fma2_(ntp, hB[q], hB[q]));
            hD[q] = fma2_(tp, cD2, fma2_(ntp, hD[q], hD[q]));
            hW[q] = fma2_(ntp, hW[q], hW[q]);
        }
    }

#pragma unroll
    for (int q = 0; q < 2; q++) {
        float r0, r1, g0, g1, b0, b1, d0, d1, w0, w1;
        upk2(hR[q], r0, r1);
        upk2(hG[q], g0, g1);
        upk2(hB[q], b0, b1);
        upk2(hD[q], d0, d1);
        upk2(hW[q], w0, w1);
        {
            int i = orig[2*q];
            out[i] = d0;
            float inv = 1.0f / (1.0f + 1e-6f - w0);
            out[NPTS + 3 * i + 0] = __saturatef(r0 * inv);
            out[NPTS + 3 * i + 1] = __saturatef(g0 * inv);
            out[NPTS + 3 * i + 2] = __saturatef(b0 * inv);
        }
        {
            int i = orig[2*q + 1];
            out[i] = d1;
            float inv = 1.0f / (1.0f + 1e-6f - w1);
            out[NPTS + 3 * i + 0] = __saturatef(r1 * inv);
            out[NPTS + 3 * i + 1] = __saturatef(g1 * inv);
            out[NPTS + 3 * i + 2] = __saturatef(b1 * inv);
        }
    }
}

extern "C" void kernel_launch(void* const* d_in, const int* in_sizes, int n_in,
                              void* d_out, int out_size)
{
    const float*  coords = (const float*)d_in[0];
    const float4* shape  = (const float4*)d_in[1];
    const float*  color  = (const float*)d_in[2];
    const float*  alpha  = (const float*)d_in[3];
    float* out = (float*)d_out;

    prep_kernel<<<(NCELLS + TPB - 1) / TPB, TPB>>>(shape, color, alpha);
    bin_kernel<<<NPTS / TPB, TPB>>>(coords, out);
    scan_kernel<<<1, 1024>>>();
    scatter_kernel<<<NPTS / (TPB * 4), TPB>>>();
    main_kernel<<<NPTS / PTS_PER_BLOCK, TPB>>>(out);
}

// round 4
// speedup vs baseline: 1.4260x; 1.4260x over previous
#include <cuda_runtime.h>

#define NPTS   2097152
#define NSTR   500
#define GRID_R 32
#define NCELLS (GRID_R * GRID_R * GRID_R)   // 32768
#define TPB    256
#define PPT    4
#define PTS_PER_BLOCK (TPB * PPT)   // 1024

typedef unsigned long long ull;
typedef unsigned int uint;

// ---- scratch (__device__ globals: allowed) ----
__device__ float4 g_tmpPts[NPTS];      // warped coords (w unused)
__device__ float4 g_sortedPts[NPTS];   // warped coords, w = orig index (bitcast)
__device__ int    g_cellOf[NPTS];
__device__ uint   g_cursor[NCELLS];    // counts -> offsets -> cursors
__device__ float4 g_s0[NSTR];          // {-cx, -cy, cr, cg}
__device__ float4 g_s1[NSTR];          // {cb, dens, -cz, b=5r+0.5}

// ---- f32x2 packed helpers (sm_103a) ----
__device__ __forceinline__ ull pk2(float lo, float hi) {
    ull r; asm("mov.b64 %0, {%1,%2};" : "=l"(r) : "f"(lo), "f"(hi)); return r;
}
__device__ __forceinline__ void upk2(ull v, float& lo, float& hi) {
    asm("mov.b64 {%0,%1}, %2;" : "=f"(lo), "=f"(hi) : "l"(v));
}
__device__ __forceinline__ ull add2(ull a, ull b) {
    ull r; asm("add.rn.f32x2 %0, %1, %2;" : "=l"(r) : "l"(a), "l"(b)); return r;
}
__device__ __forceinline__ ull mul2(ull a, ull b) {
    ull r; asm("mul.rn.f32x2 %0, %1, %2;" : "=l"(r) : "l"(a), "l"(b)); return r;
}
__device__ __forceinline__ ull fma2_(ull a, ull b, ull c) {
    ull r; asm("fma.rn.f32x2 %0, %1, %2, %3;" : "=l"(r) : "l"(a), "l"(b), "l"(c)); return r;
}
__device__ __forceinline__ float sqap(float x) {
    float y; asm("sqrt.approx.f32 %0, %1;" : "=f"(y) : "f"(x)); return y;
}
// t = saturate(dist * (-5.0) + b)   -- FFMA-imm form, rt=1
__device__ __forceinline__ float fmasat_m5(float dist, float b) {
    float d; asm("fma.rn.sat.f32 %0, %1, 0fC0A00000, %2;" : "=f"(d) : "f"(dist), "f"(b));
    return d;
}

// spread low 5 bits to positions 0,3,6,9,12 (Part1By2)
__device__ __forceinline__ uint part1by2(uint x) {
    x &= 0x3FFu;
    x = (x | (x << 16)) & 0x30000FFu;
    x = (x | (x << 8))  & 0x300F00Fu;
    x = (x | (x << 4))  & 0x30C30C3u;
    x = (x | (x << 2))  & 0x9249249u;
    return x;
}

// ---- Pass A: zero cursors + preprocess strokes ----
__global__ void prep_kernel(const float4* __restrict__ shape,
                            const float*  __restrict__ color,
                            const float*  __restrict__ alpha)
{
    int i = blockIdx.x * blockDim.x + threadIdx.x;
    if (i < NCELLS) g_cursor[i] = 0u;
    if (i < NSTR) {
        float4 sp = shape[i];
        float cr = color[3 * i + 0];
        float cg = color[3 * i + 1];
        float cb = color[3 * i + 2];
        float dens = fmaxf(alpha[i], 0.0f) * 50.0f;
        g_s0[i] = make_float4(-sp.x, -sp.y, cr, cg);
        g_s1[i] = make_float4(cb, dens, -sp.z, fmaf(sp.w, 5.0f, 0.5f));
    }
}

// ---- Pass B: warp coords, write coords output, bin-count ----
__global__ __launch_bounds__(TPB)
void bin_kernel(const float* __restrict__ coords, float* __restrict__ out)
{
    int i = blockIdx.x * TPB + threadIdx.x;
    float x = coords[3 * i + 0];
    float y = coords[3 * i + 1];
    float z = coords[3 * i + 2];
    float n2 = fmaf(x, x, fmaf(y, y, z * z));
    float n  = sqrtf(n2);
    float scale = 0.5f;
    if (n > 1.0f) scale = (2.0f - 1.0f / n) * (0.5f / n);
    float px = x * scale, py = y * scale, pz = z * scale;

    out[4 * NPTS + 3 * i + 0] = px;
    out[4 * NPTS + 3 * i + 1] = py;
    out[4 * NPTS + 3 * i + 2] = pz;
    g_tmpPts[i] = make_float4(px, py, pz, 0.0f);

    uint ix = (uint)min(GRID_R - 1, max(0, (int)((px + 1.0f) * 16.0f)));
    uint iy = (uint)min(GRID_R - 1, max(0, (int)((py + 1.0f) * 16.0f)));
    uint iz = (uint)min(GRID_R - 1, max(0, (int)((pz + 1.0f) * 16.0f)));
    int cell = (int)(part1by2(ix) | (part1by2(iy) << 1) | (part1by2(iz) << 2));
    g_cellOf[i] = cell;
    atomicAdd(&g_cursor[cell], 1u);
}

// ---- Pass C: single-block exclusive scan of 32768 counts (in place) ----
__global__ __launch_bounds__(1024)
void scan_kernel()
{
    __shared__ uint warpsum[32];
    const int t = threadIdx.x;
    const int lane = t & 31, wid = t >> 5;
    const int PER = NCELLS / 1024;   // 32

    uint v[PER];
    uint base_i = (uint)t * PER;
    uint local = 0;
#pragma unroll
    for (int j = 0; j < PER; j++) { v[j] = g_cursor[base_i + j]; local += v[j]; }

    uint x = local;
#pragma unroll
    for (int d = 1; d < 32; d <<= 1) {
        uint y = __shfl_up_sync(0xffffffffu, x, d);
        if (lane >= d) x += y;
    }
    if (lane == 31) warpsum[wid] = x;
    __syncthreads();
    if (wid == 0) {
        uint w = warpsum[lane];
#pragma unroll
        for (int d = 1; d < 32; d <<= 1) {
            uint y = __shfl_up_sync(0xffffffffu, w, d);
            if (lane >= d) w += y;
        }
        warpsum[lane] = w;
    }
    __syncthreads();
    uint base = (wid ? warpsum[wid - 1] : 0u) + (x - local);
#pragma unroll
    for (int j = 0; j < PER; j++) {
        g_cursor[base_i + j] = base;
        base += v[j];
    }
}

// ---- Pass D: scatter full point (float4, w=orig idx); 4 pts/thread for MLP ----
__global__ __launch_bounds__(TPB)
void scatter_kernel()
{
    int g = blockIdx.x * TPB + threadIdx.x;
    int4 c = ((const int4*)g_cellOf)[g];
    int i0 = g * 4;
    uint p0 = atomicAdd(&g_cursor[c.x], 1u);
    uint p1 = atomicAdd(&g_cursor[c.y], 1u);
    uint p2 = atomicAdd(&g_cursor[c.z], 1u);
    uint p3 = atomicAdd(&g_cursor[c.w], 1u);
    float4 v0 = g_tmpPts[i0 + 0]; v0.w = __int_as_float(i0 + 0);
    float4 v1 = g_tmpPts[i0 + 1]; v1.w = __int_as_float(i0 + 1);
    float4 v2 = g_tmpPts[i0 + 2]; v2.w = __int_as_float(i0 + 2);
    float4 v3 = g_tmpPts[i0 + 3]; v3.w = __int_as_float(i0 + 3);
    g_sortedPts[p0] = v0;
    g_sortedPts[p1] = v1;
    g_sortedPts[p2] = v2;
    g_sortedPts[p3] = v3;
}

// ---- Pass E: main blend over culled strokes (pair-packed f32x2) ----
__global__ __launch_bounds__(TPB)
void main_kernel(float* __restrict__ out)
{
    __shared__ float4 cs0[NSTR];
    __shared__ float4 cs1[NSTR];
    __shared__ uint  wcnt[8];
    __shared__ float red[8][6];

    const int tid = threadIdx.x;
    const int lane = tid & 31, wid = tid >> 5;
    const int base = blockIdx.x * PTS_PER_BLOCK + tid;

    float px[PPT], py[PPT], pzv[PPT];
    int   orig[PPT];

    float mnx =  1e30f, mny =  1e30f, mnz =  1e30f;
    float mxx = -1e30f, mxy = -1e30f, mxz = -1e30f;

#pragma unroll
    for (int k = 0; k < PPT; k++) {
        float4 p = g_sortedPts[base + k * TPB];
        px[k] = p.x; py[k] = p.y; pzv[k] = p.z;
        orig[k] = __float_as_int(p.w);
        mnx = fminf(mnx, p.x); mxx = fmaxf(mxx, p.x);
        mny = fminf(mny, p.y); mxy = fmaxf(mxy, p.y);
        mnz = fminf(mnz, p.z); mxz = fmaxf(mxz, p.z);
    }

    // pack points into pairs
    ull pX[2], pY[2], pZ[2];
    ull hR[2], hG[2], hB[2], hD[2], hW[2];
#pragma unroll
    for (int q = 0; q < 2; q++) {
        pX[q] = pk2(px[2*q], px[2*q+1]);
        pY[q] = pk2(py[2*q], py[2*q+1]);
        pZ[q] = pk2(pzv[2*q], pzv[2*q+1]);
        hR[q] = 0ULL; hG[q] = 0ULL; hB[q] = 0ULL; hD[q] = 0ULL;
        hW[q] = pk2(1.0f, 1.0f);
    }

    // block bbox reduce
#pragma unroll
    for (int d = 16; d; d >>= 1) {
        mnx = fminf(mnx, __shfl_xor_sync(0xffffffffu, mnx, d));
        mny = fminf(mny, __shfl_xor_sync(0xffffffffu, mny, d));
        mnz = fminf(mnz, __shfl_xor_sync(0xffffffffu, mnz, d));
        mxx = fmaxf(mxx, __shfl_xor_sync(0xffffffffu, mxx, d));
        mxy = fmaxf(mxy, __shfl_xor_sync(0xffffffffu, mxy, d));
        mxz = fmaxf(mxz, __shfl_xor_sync(0xffffffffu, mxz, d));
    }
    if (lane == 0) {
        red[wid][0] = mnx; red[wid][1] = mny; red[wid][2] = mnz;
        red[wid][3] = mxx; red[wid][4] = mxy; red[wid][5] = mxz;
    }
    __syncthreads();
#pragma unroll
    for (int ww = 0; ww < 8; ww++) {
        mnx = fminf(mnx, red[ww][0]); mny = fminf(mny, red[ww][1]); mnz = fminf(mnz, red[ww][2]);
        mxx = fmaxf(mxx, red[ww][3]); mxy = fmaxf(mxy, red[ww][4]); mxz = fmaxf(mxz, red[ww][5]);
    }
    __syncthreads();

    // ordered stream compaction of strokes intersecting the bbox
    int nlist = 0;
#pragma unroll 1
    for (int r = 0; r < 2; r++) {
        int s = r * TPB + tid;
        bool keep = false;
        float4 a0, a1;
        if (s < NSTR) {
            a0 = g_s0[s]; a1 = g_s1[s];
            float cx = -a0.x, cy = -a0.y, cz = -a1.z;
            float qx = fminf(fmaxf(cx, mnx), mxx);
            float qy = fminf(fmaxf(cy, mny), mxy);
            float qz = fminf(fmaxf(cz, mnz), mxz);
            float dx = cx - qx, dy = cy - qy, dz = cz - qz;
            float d2 = fmaf(dx, dx, fmaf(dy, dy, dz * dz));
            keep = 25.0f * d2 < a1.w * a1.w;   // dist(bbox, center) < r + 0.1
        }
        uint m = __ballot_sync(0xffffffffu, keep);
        if (lane == 0) wcnt[wid] = (uint)__popc(m);
        __syncthreads();
        int off = nlist, tot = nlist;
#pragma unroll
        for (int ww = 0; ww < 8; ww++) {
            if (ww < wid) off += (int)wcnt[ww];
            tot += (int)wcnt[ww];
        }
        if (keep) {
            int pos = off + __popc(m & ((1u << lane) - 1u));
            cs0[pos] = a0;
            cs1[pos] = a1;
        }
        nlist = tot;
        __syncthreads();
    }

    // sequential blend (order preserved), pair-packed
#pragma unroll 1
    for (int s = 0; s < nlist; s++) {
        float4 s0 = cs0[s];
        float4 s1 = cs1[s];
        ull ncx2 = pk2(s0.x, s0.x);
        ull ncy2 = pk2(s0.y, s0.y);
        ull ncz2 = pk2(s1.z, s1.z);
        ull cR2  = pk2(s0.z, s0.z);
        ull cG2  = pk2(s0.w, s0.w);
        ull cB2  = pk2(s1.x, s1.x);
        ull cD2  = pk2(s1.y, s1.y);
        float bb = s1.w;
#pragma unroll
        for (int q = 0; q < 2; q++) {
            ull dX = add2(pX[q], ncx2);
            ull dY = add2(pY[q], ncy2);
            ull dZ = add2(pZ[q], ncz2);
            ull d2p = fma2_(dZ, dZ, fma2_(dY, dY, mul2(dX, dX)));
            float d2a, d2b; upk2(d2p, d2a, d2b);
            float ta = fmasat_m5(sqap(d2a), bb);
            float tb = fmasat_m5(sqap(d2b), bb);
            ull tp  = pk2(ta, tb);
            ull ntp = tp ^ 0x8000000080000000ULL;   // (-ta, -tb) : alu pipe
            hR[q] = fma2_(tp, cR2, fma2_(ntp, hR[q], hR[q]));
            hG[q] = fma2_(tp, cG2, fma2_(ntp, hG[q], hG[q]));
            hB[q] = fma2_(tp, cB2, fma2_(ntp, hB[q], hB[q]));
            hD[q] = fma2_(tp, cD2, fma2_(ntp, hD[q], hD[q]));
            hW[q] = fma2_(ntp, hW[q], hW[q]);
        }
    }

#pragma unroll
    for (int q = 0; q < 2; q++) {
        float r0, r1, g0, g1, b0, b1, d0, d1, w0, w1;
        upk2(hR[q], r0, r1);
        upk2(hG[q], g0, g1);
        upk2(hB[q], b0, b1);
        upk2(hD[q], d0, d1);
        upk2(hW[q], w0, w1);
        {
            int i = orig[2*q];
            out[i] = d0;
            float inv = 1.0f / (1.0f + 1e-6f - w0);
            out[NPTS + 3 * i + 0] = __saturatef(r0 * inv);
            out[NPTS + 3 * i + 1] = __saturatef(g0 * inv);
            out[NPTS + 3 * i + 2] = __saturatef(b0 * inv);
        }
        {
            int i = orig[2*q + 1];
            out[i] = d1;
            float inv = 1.0f / (1.0f + 1e-6f - w1);
            out[NPTS + 3 * i + 0] = __saturatef(r1 * inv);
            out[NPTS + 3 * i + 1] = __saturatef(g1 * inv);
            out[NPTS + 3 * i + 2] = __saturatef(b1 * inv);
        }
    }
}

extern "C" void kernel_launch(void* const* d_in, const int* in_sizes, int n_in,
                              void* d_out, int out_size)
{
    const float*  coords = (const float*)d_in[0];
    const float4* shape  = (const float4*)d_in[1];
    const float*  color  = (const float*)d_in[2];
    const float*  alpha  = (const float*)d_in[3];
    float* out = (float*)d_out;

    prep_kernel<<<(NCELLS + TPB - 1) / TPB, TPB>>>(shape, color, alpha);
    bin_kernel<<<NPTS / TPB, TPB>>>(coords, out);
    scan_kernel<<<1, 1024>>>();
    scatter_kernel<<<NPTS / (TPB * 4), TPB>>>();
    main_kernel<<<NPTS / PTS_PER_BLOCK, TPB>>>(out);
}